// round 2
// baseline (speedup 1.0000x reference)
#include <cuda_runtime.h>
#include <stdint.h>

// winner[s] = (largest sample index p that writes slot s) + 1, or 0 if none.
// Zero-initialized at module load; rs_gather_kernel resets it to 0 after
// consuming, so every kernel_launch call (and graph replay) starts clean.
#define N_SLOTS 16384
#define D_DIM   256

__device__ int g_winner[N_SLOTS];

// K1: each sample p computes its target slot and atomicMax's (p+1) in.
// 4 samples per thread via float4 loads of u.
__global__ void rs_scatter_kernel(const float4* __restrict__ u4,
                                  const int* __restrict__ i0_ptr,
                                  int b, int n) {
    int t = blockIdx.x * blockDim.x + threadIdx.x;
    int p0 = t * 4;
    if (p0 >= b) return;
    int i0 = *i0_ptr;
    float4 uv = u4[t];
    float uu[4] = {uv.x, uv.y, uv.z, uv.w};
#pragma unroll
    for (int k = 0; k < 4; k++) {
        int p = p0 + k;
        int pos = i0 + p;
        int idx;
        if (pos < n) {
            idx = pos;                     // deterministic fill phase
        } else {
            // match JAX exactly: floor(u * float(pos+1)) in f32, clamp to pos
            float prod = uu[k] * (float)(pos + 1);
            int r = (int)floorf(prod);
            idx = r < pos ? r : pos;
        }
        if (idx < n) {
            atomicMax(&g_winner[idx], p + 1);
        }
    }
}

// K2: gather winning rows (or keep old buffer row) into the output, then
// reset the winner slots to 0. Each block owns 4 rows (256 threads, 64/row),
// so the read->reset of g_winner[s] races with nothing outside the block.
__global__ void rs_gather_kernel(const float4* __restrict__ samples,
                                 const float4* __restrict__ buffer,
                                 float4* __restrict__ out) {
    __shared__ int sh_w[4];
    int row0 = blockIdx.x * 4;
    int r  = threadIdx.x >> 6;          // 0..3: row within block
    int d4 = threadIdx.x & 63;          // 0..63: float4 within row
    int s = row0 + r;
    if (d4 == 0) {
        int w = g_winner[s];
        sh_w[r] = w;
        g_winner[s] = 0;                // self-clean for the next replay
    }
    __syncthreads();
    int w = sh_w[r];
    const float4* src = (w > 0) ? (samples + (size_t)(w - 1) * (D_DIM / 4))
                                : (buffer  + (size_t)s * (D_DIM / 4));
    out[(size_t)s * (D_DIM / 4) + d4] = src[d4];
}

extern "C" void kernel_launch(void* const* d_in, const int* in_sizes, int n_in,
                              void* d_out, int out_size) {
    const float* samples = (const float*)d_in[0];   // [B, 256]
    const float* buffer  = (const float*)d_in[1];   // [N, 256]
    const float* u       = (const float*)d_in[2];   // [B]
    const int*   i0      = (const int*)d_in[3];     // scalar

    int b = in_sizes[2];                // B from u's element count
    int n = in_sizes[1] / D_DIM;        // N from buffer element count

    // K1: scatter sample indices (p+1) with atomicMax; 4 samples/thread
    int threads1 = (b + 3) / 4;
    rs_scatter_kernel<<<(threads1 + 255) / 256, 256>>>(
        (const float4*)u, i0, b, n);

    // K2: gather rows into output + reset winners (4 rows per block)
    rs_gather_kernel<<<n / 4, 256>>>(
        (const float4*)samples, (const float4*)buffer, (float4*)d_out);
}

// round 3
// speedup vs baseline: 3.3673x; 3.3673x over previous
#include <cuda_runtime.h>
#include <stdint.h>

// winner[s] = (largest sample index p that writes slot s) + 1, or 0 if none.
// Zero-initialized at module load; rs_gather_kernel resets consumed entries
// to 0, so every kernel_launch call (and graph replay) starts clean.
#define N_SLOTS 16384
#define D_DIM   256
#define ROW_F4  (D_DIM / 4)   // 64 float4 per row

__device__ int g_winner[N_SLOTS];

// K1: each sample p computes its target slot and atomicMax's (p+1) in.
// 4 samples per thread via float4 loads of u.
__global__ void rs_scatter_kernel(const float4* __restrict__ u4,
                                  const int* __restrict__ i0_ptr,
                                  int b, int n) {
    int t = blockIdx.x * blockDim.x + threadIdx.x;
    int p0 = t * 4;
    if (p0 >= b) return;
    int i0 = *i0_ptr;
    float4 uv = u4[t];
    float uu[4] = {uv.x, uv.y, uv.z, uv.w};
#pragma unroll
    for (int k = 0; k < 4; k++) {
        int p = p0 + k;
        int pos = i0 + p;
        int idx;
        if (pos < n) {
            idx = pos;                     // deterministic fill phase
        } else {
            // match JAX exactly: floor(u * float(pos+1)) in f32, clamp to pos
            float prod = uu[k] * (float)(pos + 1);
            int r = (int)floorf(prod);
            idx = r < pos ? r : pos;
        }
        if (idx < n) {
            atomicMax(&g_winner[idx], p + 1);
        }
    }
}

// K2: gather winning rows (or keep old buffer row) into the output, and
// reset consumed winner slots to 0 for the next replay.
// One warp per row; no shared memory, no barriers:
//   - all 32 lanes LDG g_winner[s] (warp-uniform -> one broadcast request)
//   - lane 0 stores 0, data-dependent on the loaded value (ordered after
//     the load in program order; no other warp owns slot s)
//   - each lane moves 2 independent float4s (MLP=2 per lane)
__global__ void rs_gather_kernel(const float4* __restrict__ samples,
                                 const float4* __restrict__ buffer,
                                 float4* __restrict__ out) {
    int gtid = blockIdx.x * blockDim.x + threadIdx.x;
    int s    = gtid >> 5;           // row = global warp id
    int lane = threadIdx.x & 31;

    int w = g_winner[s];            // broadcast load, all lanes
    if (lane == 0 && w != 0) {
        g_winner[s] = 0;            // self-clean; depends on w -> after load
    }

    const float4* src = (w > 0) ? (samples + (size_t)(w - 1) * ROW_F4)
                                : (buffer  + (size_t)s * ROW_F4);
    float4 a = src[lane];
    float4 c = src[lane + 32];
    float4* o = out + (size_t)s * ROW_F4;
    o[lane]      = a;
    o[lane + 32] = c;
}

extern "C" void kernel_launch(void* const* d_in, const int* in_sizes, int n_in,
                              void* d_out, int out_size) {
    const float* samples = (const float*)d_in[0];   // [B, 256]
    const float* buffer  = (const float*)d_in[1];   // [N, 256]
    const float* u       = (const float*)d_in[2];   // [B]
    const int*   i0      = (const int*)d_in[3];     // scalar

    int b = in_sizes[2];                // B from u's element count
    int n = in_sizes[1] / D_DIM;        // N from buffer element count

    // K1: scatter sample indices (p+1) with atomicMax; 4 samples/thread
    int threads1 = (b + 3) / 4;
    rs_scatter_kernel<<<(threads1 + 255) / 256, 256>>>(
        (const float4*)u, i0, b, n);

    // K2: one warp per row -> n warps -> n*32 threads
    rs_gather_kernel<<<(n * 32) / 256, 256>>>(
        (const float4*)samples, (const float4*)buffer, (float4*)d_out);
}

// round 4
// speedup vs baseline: 3.4478x; 1.0239x over previous
#include <cuda_runtime.h>
#include <stdint.h>

// winner[s] = (largest sample index p that writes slot s) + 1, or 0 if none.
// Zero-initialized at module load; rs_gather_kernel resets consumed entries
// to 0, so every kernel_launch call (and graph replay) starts clean.
#define N_SLOTS 16384
#define D_DIM   256
#define ROW_F4  (D_DIM / 4)   // 64 float4 per row

__device__ int g_winner[N_SLOTS];

// K1: each sample p computes its target slot and atomicMax's (p+1) in.
// 4 samples per thread via float4 loads of u.
__global__ void rs_scatter_kernel(const float4* __restrict__ u4,
                                  const int* __restrict__ i0_ptr,
                                  int b, int n) {
    int t = blockIdx.x * blockDim.x + threadIdx.x;
    int p0 = t * 4;
    if (p0 >= b) return;
    int i0 = *i0_ptr;
    float4 uv = u4[t];
    float uu[4] = {uv.x, uv.y, uv.z, uv.w};
#pragma unroll
    for (int k = 0; k < 4; k++) {
        int p = p0 + k;
        int pos = i0 + p;
        int idx;
        if (pos < n) {
            idx = pos;                     // deterministic fill phase
        } else {
            // match JAX exactly: floor(u * float(pos+1)) in f32, clamp to pos
            float prod = uu[k] * (float)(pos + 1);
            int r = (int)floorf(prod);
            idx = r < pos ? r : pos;
        }
        if (idx < n) {
            atomicMax(&g_winner[idx], p + 1);
        }
    }
}

// K2: gather winning rows (or keep old buffer row) into the output, and
// reset consumed winner slots to 0 for the next replay.
// One warp per row; no shared memory, no barriers:
//   - all 32 lanes LDG g_winner[s] (warp-uniform -> one broadcast request)
//   - lane 0 stores 0, data-dependent on the loaded value (ordered after
//     the load in program order; no other warp owns slot s)
//   - each lane moves 2 independent float4s (MLP=2 per lane)
__global__ void rs_gather_kernel(const float4* __restrict__ samples,
                                 const float4* __restrict__ buffer,
                                 float4* __restrict__ out) {
    int gtid = blockIdx.x * blockDim.x + threadIdx.x;
    int s    = gtid >> 5;           // row = global warp id
    int lane = threadIdx.x & 31;

    int w = g_winner[s];            // broadcast load, all lanes
    if (lane == 0 && w != 0) {
        g_winner[s] = 0;            // self-clean; depends on w -> after load
    }

    const float4* src = (w > 0) ? (samples + (size_t)(w - 1) * ROW_F4)
                                : (buffer  + (size_t)s * ROW_F4);
    float4 a = src[lane];
    float4 c = src[lane + 32];
    float4* o = out + (size_t)s * ROW_F4;
    o[lane]      = a;
    o[lane + 32] = c;
}

extern "C" void kernel_launch(void* const* d_in, const int* in_sizes, int n_in,
                              void* d_out, int out_size) {
    const float* samples = (const float*)d_in[0];   // [B, 256]
    const float* buffer  = (const float*)d_in[1];   // [N, 256]
    const float* u       = (const float*)d_in[2];   // [B]
    const int*   i0      = (const int*)d_in[3];     // scalar

    int b = in_sizes[2];                // B from u's element count
    int n = in_sizes[1] / D_DIM;        // N from buffer element count

    // K1: scatter sample indices (p+1) with atomicMax; 4 samples/thread
    int threads1 = (b + 3) / 4;
    rs_scatter_kernel<<<(threads1 + 255) / 256, 256>>>(
        (const float4*)u, i0, b, n);

    // K2: one warp per row -> n warps -> n*32 threads
    rs_gather_kernel<<<(n * 32) / 256, 256>>>(
        (const float4*)samples, (const float4*)buffer, (float4*)d_out);
}